// round 4
// baseline (speedup 1.0000x reference)
#include <cuda_runtime.h>
#include <math.h>

// ---------------------------------------------------------------------------
// GraphUnet: N=4096, DIM=320, L=2, KS=(0.8,0.6) -> kk0=3276, kk1=1965
// ---------------------------------------------------------------------------
#define N0   4096
#define DD   320
#define DD2  640
#define KK0  3276
#define KK1  1965
#define NW   128          // bitmask words per row (4096/32)

// ---- packed split-weight buffer offsets (float2 elements) ----
#define OFF_W0     0
#define OFF_DW0    102400
#define OFF_DW1    204800
#define OFF_WB     307200
#define OFF_CATW0  409600
#define OFF_CATW1  614400
#define OFF_AGP0   819200
#define OFF_AGP1   921600
#define OFF_UW0    1024000
#define OFF_UW1    1228800
#define OFF_WE     1433600
#define OFF_XIN    1638400
#define SPLIT_TOT  2949120

// ---------------- static scratch (no allocations allowed) ------------------
__device__ float2   g_Ws  [SPLIT_TOT];     // split weights + Xin
__device__ float2   g_X0s [N0*DD];
__device__ float2   g_X1ds[N0*DD];
__device__ float2   g_X1s [N0*DD];
__device__ float2   g_X2s [N0*DD];
__device__ float2   g_Gs  [N0*DD];
__device__ float2   g_catS[N0*DD2];
__device__ float    g_X0 [N0*DD];
__device__ float    g_X1d[N0*DD];
__device__ float    g_X2d[N0*DD];
__device__ float    g_Xb [N0*DD];
__device__ float    g_Xu1[N0*DD];
__device__ float    g_Xu0[N0*DD];
__device__ unsigned g_bm [N0*NW];
__device__ float    g_h1 [N0];
__device__ float    g_e  [N0];
__device__ float    g_eh [N0];
__device__ float    g_sc [N0];
__device__ float    g_vals0[N0];
__device__ float    g_vals1[N0];
__device__ int      g_idx0[N0];
__device__ int      g_idx1[N0];
__device__ float    g_biasGS[2*DD];

// ---------------------------------------------------------------------------
// helpers
// ---------------------------------------------------------------------------
__device__ __forceinline__ unsigned tf32_rna(float x) {
    unsigned r;
    asm("cvt.rna.tf32.f32 %0, %1;" : "=r"(r) : "f"(x));
    return r;
}
__device__ __forceinline__ float2 split2(float x) {
    unsigned big = tf32_rna(x);
    float bf = __uint_as_float(big);
    unsigned sml = tf32_rna(x - bf);
    return make_float2(bf, __uint_as_float(sml));
}

__device__ __forceinline__ void mma_tf32(float* d, const unsigned* a, const unsigned* b) {
    asm volatile(
        "mma.sync.aligned.m16n8k8.row.col.f32.tf32.tf32.f32 "
        "{%0,%1,%2,%3}, {%4,%5,%6,%7}, {%8,%9}, {%0,%1,%2,%3};"
        : "+f"(d[0]), "+f"(d[1]), "+f"(d[2]), "+f"(d[3])
        : "r"(a[0]), "r"(a[1]), "r"(a[2]), "r"(a[3]), "r"(b[0]), "r"(b[1]));
}

__device__ __forceinline__ void cp_async16(unsigned daddr, const void* gptr, int src_bytes) {
    asm volatile("cp.async.cg.shared.global [%0], [%1], 16, %2;"
                 :: "r"(daddr), "l"(gptr), "r"(src_bytes));
}

// ---------------------------------------------------------------------------
// One-shot split of all weights + Xin into g_Ws
// ---------------------------------------------------------------------------
__global__ void split_all_kernel(
    const float* __restrict__ W0, const float* __restrict__ dW,
    const float* __restrict__ Wb, const float* __restrict__ agWg,
    const float* __restrict__ agWs, const float* __restrict__ agWp,
    const float* __restrict__ uW, const float* __restrict__ We,
    const float* __restrict__ Xin, float2* __restrict__ out)
{
    int gid = blockIdx.x * blockDim.x + threadIdx.x;
    if (gid >= SPLIT_TOT) return;
    int off = gid;
    float x;
    if (off < 102400)                       x = W0[off];
    else if ((off -= 102400) < 204800)      x = dW[off];
    else if ((off -= 204800) < 102400)      x = Wb[off];
    else if ((off -= 102400) < 102400)      x = agWg[off];
    else if ((off -= 102400) < 102400)      x = agWs[off];
    else if ((off -= 102400) < 102400)      x = agWg[102400 + off];
    else if ((off -= 102400) < 102400)      x = agWs[102400 + off];
    else if ((off -= 102400) < 204800)      x = agWp[off];
    else if ((off -= 204800) < 409600)      x = uW[off];
    else if ((off -= 409600) < 204800)      x = We[off];
    else { off -= 204800;                   x = Xin[off]; }
    out[gid] = split2(x);
}

// ---------------------------------------------------------------------------
// Bitmask build
// ---------------------------------------------------------------------------
__global__ void build_mask_kernel(const float* __restrict__ A, unsigned* __restrict__ bm) {
    int gid = blockIdx.x * blockDim.x + threadIdx.x;
    float v = A[gid];
    unsigned b = __ballot_sync(0xffffffffu, v != 0.0f);
    if ((threadIdx.x & 31) == 0) bm[gid >> 5] = b;
}

// ---------------------------------------------------------------------------
// 3xTF32 tensor-core GEMM on PRE-SPLIT operands (float2 = {big, small}).
// C fp32 and/or Cs split output, either may be null.
// CTA: 128 threads (4 warps 2x2), tile 64x64, BK=32, cp.async 2-stage.
// N multiple of 64, K multiple of 32. act: 0 none, 1 relu, 2 sigmoid.
// lda/ldb/ldcs in float2 elements; ldc/ldres in floats.
// ---------------------------------------------------------------------------
#define APITCH 36
#define BPITCH 68
#define SMEM_GEMM ((2*64*APITCH + 2*32*BPITCH) * (int)sizeof(float2))

__global__ __launch_bounds__(128) void gemm_tc_kernel(
    int M, int K,
    const float2* __restrict__ A, int lda,
    const float2* __restrict__ B, int ldb,
    const float* __restrict__ bias,
    float* __restrict__ C, int ldc,
    float2* __restrict__ Cs, int ldcs,
    const float* __restrict__ res, int ldres,
    int act)
{
    extern __shared__ float2 smem2[];
    float2* Asm = smem2;                       // [2][64][APITCH]
    float2* Bsm = smem2 + 2 * 64 * APITCH;     // [2][32][BPITCH]

    const int tid  = threadIdx.x;
    const int wid  = tid >> 5;
    const int lane = tid & 31;
    const int wm   = wid & 1;
    const int wn   = wid >> 1;
    const int g    = lane >> 2;
    const int tg   = lane & 3;

    const int row0 = blockIdx.y * 64;
    const int col0 = blockIdx.x * 64;

    unsigned asBase = (unsigned)__cvta_generic_to_shared(Asm);
    unsigned bsBase = (unsigned)__cvta_generic_to_shared(Bsm);

    float acc[2][4][4];
#pragma unroll
    for (int mt = 0; mt < 2; mt++)
#pragma unroll
        for (int nt = 0; nt < 4; nt++)
#pragma unroll
            for (int j = 0; j < 4; j++) acc[mt][nt][j] = 0.f;

    const int nt_k = K / 32;

    auto issue_stage = [&](int kt, int s) {
        const int k0 = kt * 32;               // float2 elements along K
        // A tile: 64 rows x 32 f2 = 1024 x 16B chunks, 8 per thread
#pragma unroll
        for (int i = 0; i < 8; i++) {
            int idx = i * 128 + tid;
            int r = idx >> 4, c2 = (idx & 15) * 2;
            int gr = row0 + r;
            int pr = (gr < M) ? 16 : 0;
            int grc = gr < M ? gr : (M - 1);
            const float2* gp = A + (size_t)grc * lda + k0 + c2;
            unsigned daddr = asBase + (unsigned)(((s * 64 + r) * APITCH + c2) * 8);
            cp_async16(daddr, gp, pr);
        }
        // B tile: 32 rows x 64 f2 = 1024 x 16B chunks, 8 per thread
#pragma unroll
        for (int i = 0; i < 8; i++) {
            int idx = i * 128 + tid;
            int kr = idx >> 5, c2 = (idx & 31) * 2;
            const float2* gp = B + (size_t)(k0 + kr) * ldb + col0 + c2;
            unsigned daddr = bsBase + (unsigned)(((s * 32 + kr) * BPITCH + c2) * 8);
            cp_async16(daddr, gp, 16);
        }
        asm volatile("cp.async.commit_group;");
    };

    issue_stage(0, 0);

    for (int kt = 0; kt < nt_k; kt++) {
        asm volatile("cp.async.wait_group 0;");
        __syncthreads();
        if (kt + 1 < nt_k) issue_stage(kt + 1, (kt + 1) & 1);

        const int buf = kt & 1;
        const float2* Ab = Asm + buf * 64 * APITCH;
        const float2* Bb = Bsm + buf * 32 * BPITCH;

#pragma unroll
        for (int kk = 0; kk < 4; kk++) {
            const int kc = kk * 8;
            unsigned abg[2][4], asml[2][4];
#pragma unroll
            for (int mt = 0; mt < 2; mt++) {
                const int rb = wm * 32 + mt * 16;
                float2 x0 = Ab[(rb + g) * APITCH + kc + tg];
                float2 x1 = Ab[(rb + g + 8) * APITCH + kc + tg];
                float2 x2 = Ab[(rb + g) * APITCH + kc + tg + 4];
                float2 x3 = Ab[(rb + g + 8) * APITCH + kc + tg + 4];
                abg[mt][0] = __float_as_uint(x0.x);  asml[mt][0] = __float_as_uint(x0.y);
                abg[mt][1] = __float_as_uint(x1.x);  asml[mt][1] = __float_as_uint(x1.y);
                abg[mt][2] = __float_as_uint(x2.x);  asml[mt][2] = __float_as_uint(x2.y);
                abg[mt][3] = __float_as_uint(x3.x);  asml[mt][3] = __float_as_uint(x3.y);
            }
            unsigned bbg[4][2], bsm[4][2];
#pragma unroll
            for (int nt = 0; nt < 4; nt++) {
                const int cb = wn * 32 + nt * 8;
                float2 y0 = Bb[(kc + tg) * BPITCH + cb + g];
                float2 y1 = Bb[(kc + tg + 4) * BPITCH + cb + g];
                bbg[nt][0] = __float_as_uint(y0.x);  bsm[nt][0] = __float_as_uint(y0.y);
                bbg[nt][1] = __float_as_uint(y1.x);  bsm[nt][1] = __float_as_uint(y1.y);
            }
#pragma unroll
            for (int mt = 0; mt < 2; mt++)
#pragma unroll
                for (int nt = 0; nt < 4; nt++) {
                    mma_tf32(acc[mt][nt], abg[mt], bbg[nt]);
                    mma_tf32(acc[mt][nt], abg[mt], bsm[nt]);
                    mma_tf32(acc[mt][nt], asml[mt], bbg[nt]);
                }
        }
        __syncthreads();
    }

    // ---- epilogue ----
#pragma unroll
    for (int mt = 0; mt < 2; mt++) {
#pragma unroll
        for (int nt = 0; nt < 4; nt++) {
            const int col = col0 + wn * 32 + nt * 8 + tg * 2;
            float b0 = bias[col], b1 = bias[col + 1];
#pragma unroll
            for (int h = 0; h < 2; h++) {
                const int r = row0 + wm * 32 + mt * 16 + g + h * 8;
                if (r >= M) continue;
                float v0 = acc[mt][nt][h * 2 + 0] + b0;
                float v1 = acc[mt][nt][h * 2 + 1] + b1;
                if (act == 1) {
                    v0 = fmaxf(v0, 0.f); v1 = fmaxf(v1, 0.f);
                } else if (act == 2) {
                    v0 = 1.f / (1.f + expf(-v0));
                    v1 = 1.f / (1.f + expf(-v1));
                }
                if (res) {
                    v0 += res[(size_t)r * ldres + col];
                    v1 += res[(size_t)r * ldres + col + 1];
                }
                if (C) {
                    float2* cp = reinterpret_cast<float2*>(C + (size_t)r * ldc + col);
                    *cp = make_float2(v0, v1);
                }
                if (Cs) {
                    float2* sp = Cs + (size_t)r * ldcs + col;
                    sp[0] = split2(v0);
                    sp[1] = split2(v1);
                }
            }
        }
    }
}

// ---------------------------------------------------------------------------
// Fused GEMV + e/eh
// ---------------------------------------------------------------------------
__global__ void gemv_e_kernel(int M, const float* __restrict__ X,
                              const float* __restrict__ w,
                              const float* __restrict__ pwb,
                              const float* __restrict__ pb,
                              const float* __restrict__ phi0,
                              float* __restrict__ h1,
                              float* __restrict__ e, float* __restrict__ eh)
{
    int warp = (blockIdx.x * blockDim.x + threadIdx.x) >> 5;
    int lane = threadIdx.x & 31;
    if (warp >= M) return;
    const float* xr = X + (size_t)warp * DD;
    float s = 0.f;
    for (int k = lane; k < DD; k += 32) s += xr[k] * w[k];
#pragma unroll
    for (int o = 16; o > 0; o >>= 1) s += __shfl_down_sync(0xffffffffu, s, o);
    if (lane == 0) {
        float h = s + pwb[0] + pb[0];
        float ex = expf(phi0[0] * h);
        h1[warp] = h;
        e[warp] = ex;
        eh[warp] = ex * h;
    }
}

__global__ void agg0_kernel(const unsigned* __restrict__ bm,
                            const float* __restrict__ e,
                            const float* __restrict__ eh,
                            float* __restrict__ scores)
{
    int r = blockIdx.x;
    int t = threadIdx.x;
    unsigned w = bm[r * NW + t];
    if ((r >> 5) == t) w |= (1u << (r & 31));
    float se = 0.f, sh = 0.f;
    while (w) {
        int b = __ffs(w) - 1;
        w &= w - 1;
        int j = t * 32 + b;
        se += e[j];
        sh += eh[j];
    }
    __shared__ float s1[128], s2[128];
    s1[t] = se; s2[t] = sh;
    __syncthreads();
    for (int o = 64; o > 0; o >>= 1) {
        if (t < o) { s1[t] += s1[t + o]; s2[t] += s2[t + o]; }
        __syncthreads();
    }
    if (t == 0) {
        float agg = (s2[0] / s1[0]) * 0.01f;
        scores[r] = 1.f / (1.f + expf(-agg));
    }
}

__global__ void agg1_kernel(const unsigned* __restrict__ bm,
                            const int* __restrict__ idx0, int n1,
                            const float* __restrict__ e,
                            const float* __restrict__ eh,
                            float* __restrict__ scores)
{
    __shared__ unsigned row[NW];
    int r = blockIdx.x;
    int t = threadIdx.x;
    int orig = idx0[r];
    if (t < NW) row[t] = bm[orig * NW + t];
    __syncthreads();
    float se = 0.f, sh = 0.f;
    for (int j = t; j < n1; j += 256) {
        int c = idx0[j];
        bool in = (row[c >> 5] >> (c & 31)) & 1u;
        if (j == r) in = true;
        if (in) { se += e[j]; sh += eh[j]; }
    }
    __shared__ float s1[256], s2[256];
    s1[t] = se; s2[t] = sh;
    __syncthreads();
    for (int o = 128; o > 0; o >>= 1) {
        if (t < o) { s1[t] += s1[t + o]; s2[t] += s2[t + o]; }
        __syncthreads();
    }
    if (t == 0) {
        float agg = (s2[0] / s1[0]) * 0.01f;
        scores[r] = 1.f / (1.f + expf(-agg));
    }
}

// Stable top-k by full rank (matches jax.lax.top_k order exactly)
__global__ void rank_select_kernel(const float* __restrict__ s, int n, int kk,
                                   int* __restrict__ idx, float* __restrict__ vals)
{
    __shared__ float sh[256];
    int i = blockIdx.x * blockDim.x + threadIdx.x;
    float si = (i < n) ? s[i] : 0.f;
    int rank = 0;
    for (int base = 0; base < n; base += 256) {
        int j = base + threadIdx.x;
        sh[threadIdx.x] = (j < n) ? s[j] : -3.0e38f;
        __syncthreads();
        int lim = min(256, n - base);
        for (int t = 0; t < lim; t++) {
            float sj = sh[t];
            int j2 = base + t;
            if (sj > si || (sj == si && j2 < i)) rank++;
        }
        __syncthreads();
    }
    if (i < n && rank < kk) { idx[rank] = i; vals[rank] = si; }
}

// dst split = split(src[idx[r],:] * vals[r]);  used only as GEMM-A
__global__ void gather_scale_split_kernel(const float* __restrict__ src,
                                          const int* __restrict__ idx,
                                          const float* __restrict__ vals,
                                          int rows, float2* __restrict__ dst)
{
    int gid = blockIdx.x * blockDim.x + threadIdx.x;
    if (gid >= rows * DD) return;
    int r = gid / DD, c = gid % DD;
    dst[gid] = split2(src[(size_t)idx[r] * DD + c] * vals[r]);
}

// zero cols [0,DD) of a split matrix with row stride DD2
__global__ void zero_cols_split_kernel(float2* __restrict__ p, int rows) {
    int gid = blockIdx.x * blockDim.x + threadIdx.x;
    if (gid >= rows * DD) return;
    int r = gid / DD, c = gid % DD;
    p[(size_t)r * DD2 + c] = make_float2(0.f, 0.f);
}

// dst split[idx[r]*DD2 + c] = split(src[r*DD + c])
__global__ void scatter_split_kernel(float2* __restrict__ dst,
                                     const int* __restrict__ idx,
                                     const float* __restrict__ src, int rows)
{
    int gid = blockIdx.x * blockDim.x + threadIdx.x;
    if (gid >= rows * DD) return;
    int r = gid / DD, c = gid % DD;
    dst[(size_t)idx[r] * DD2 + c] = split2(src[gid]);
}

// dst split[r*DD2 + c] = split(src[r*DD + c])  (dst pre-offset by column)
__global__ void copy_split_kernel(float2* __restrict__ dst,
                                  const float* __restrict__ src, int rows)
{
    int gid = blockIdx.x * blockDim.x + threadIdx.x;
    if (gid >= rows * DD) return;
    int r = gid / DD, c = gid % DD;
    dst[(size_t)r * DD2 + c] = split2(src[gid]);
}

__global__ void add_bias_kernel(const float* __restrict__ a,
                                const float* __restrict__ b,
                                float* __restrict__ o, int n)
{
    int gid = blockIdx.x * blockDim.x + threadIdx.x;
    if (gid < n) o[gid] = a[gid] + b[gid];
}

// ---------------------------------------------------------------------------
extern "C" void kernel_launch(void* const* d_in, const int* in_sizes, int n_in,
                              void* d_out, int out_size)
{
    const float* A     = (const float*)d_in[0];
    const float* Xin   = (const float*)d_in[1];
    const float* W0    = (const float*)d_in[2];
    const float* b0    = (const float*)d_in[3];
    const float* Wb    = (const float*)d_in[4];
    const float* bb    = (const float*)d_in[5];
    const float* We    = (const float*)d_in[6];
    const float* be    = (const float*)d_in[7];
    const float* dW    = (const float*)d_in[8];
    const float* db    = (const float*)d_in[9];
    const float* uW    = (const float*)d_in[10];
    const float* ub    = (const float*)d_in[11];
    const float* pW    = (const float*)d_in[12];
    const float* pwb   = (const float*)d_in[13];
    const float* pb    = (const float*)d_in[14];
    const float* phi   = (const float*)d_in[15];
    const float* agWg  = (const float*)d_in[16];
    const float* agbg  = (const float*)d_in[17];
    const float* agWs  = (const float*)d_in[18];
    const float* agbs  = (const float*)d_in[19];
    const float* agWp  = (const float*)d_in[20];
    const float* agbp  = (const float*)d_in[21];

    float *X0, *X1d, *X2d, *Xb, *Xu1, *Xu0;
    float *h1, *e, *eh, *sc, *vals0, *vals1, *biasGS;
    float2 *Ws, *X0s, *X1ds, *X1s, *X2s, *Gs, *catS;
    int *idx0, *idx1;
    unsigned* bm;
    cudaGetSymbolAddress((void**)&Ws,   g_Ws);
    cudaGetSymbolAddress((void**)&X0s,  g_X0s);
    cudaGetSymbolAddress((void**)&X1ds, g_X1ds);
    cudaGetSymbolAddress((void**)&X1s,  g_X1s);
    cudaGetSymbolAddress((void**)&X2s,  g_X2s);
    cudaGetSymbolAddress((void**)&Gs,   g_Gs);
    cudaGetSymbolAddress((void**)&catS, g_catS);
    cudaGetSymbolAddress((void**)&X0,  g_X0);
    cudaGetSymbolAddress((void**)&X1d, g_X1d);
    cudaGetSymbolAddress((void**)&X2d, g_X2d);
    cudaGetSymbolAddress((void**)&Xb,  g_Xb);
    cudaGetSymbolAddress((void**)&Xu1, g_Xu1);
    cudaGetSymbolAddress((void**)&Xu0, g_Xu0);
    cudaGetSymbolAddress((void**)&bm,  g_bm);
    cudaGetSymbolAddress((void**)&h1,  g_h1);
    cudaGetSymbolAddress((void**)&e,   g_e);
    cudaGetSymbolAddress((void**)&eh,  g_eh);
    cudaGetSymbolAddress((void**)&sc,  g_sc);
    cudaGetSymbolAddress((void**)&vals0, g_vals0);
    cudaGetSymbolAddress((void**)&vals1, g_vals1);
    cudaGetSymbolAddress((void**)&idx0, g_idx0);
    cudaGetSymbolAddress((void**)&idx1, g_idx1);
    cudaGetSymbolAddress((void**)&biasGS, g_biasGS);

    cudaFuncSetAttribute(gemm_tc_kernel,
                         cudaFuncAttributeMaxDynamicSharedMemorySize, SMEM_GEMM);

    auto gemm = [&](int M, int N, int K,
                    const float2* Ap, int lda, const float2* Bp, int ldb,
                    const float* bias, float* Cp, int ldc,
                    float2* Csp, int ldcs,
                    const float* res, int ldres, int act) {
        dim3 grid(N / 64, (M + 63) / 64);
        gemm_tc_kernel<<<grid, 128, SMEM_GEMM>>>(M, K, Ap, lda, Bp, ldb, bias,
                                                 Cp, ldc, Csp, ldcs, res, ldres, act);
    };

    // ---- setup ----
    split_all_kernel<<<(SPLIT_TOT + 255) / 256, 256>>>(W0, dW, Wb, agWg, agWs,
                                                       agWp, uW, We, Xin, Ws);
    build_mask_kernel<<<(N0 * N0) / 256, 256>>>(A, bm);
    add_bias_kernel<<<3, 256>>>(agbg, agbs, biasGS, 2 * DD);

    // ---- encoder / down path ----
    gemm(N0, DD, DD, Ws + OFF_XIN, DD, Ws + OFF_W0, DD, b0, X0, DD, X0s, DD, nullptr, 0, 1);
    gemm(N0, DD, DD, X0s, DD, Ws + OFF_DW0, DD, db, X1d, DD, X1ds, DD, nullptr, 0, 1);

    gemv_e_kernel<<<(N0 + 7) / 8, 256>>>(N0, X1d, pW, pwb, pb, phi, h1, e, eh);
    agg0_kernel<<<N0, 128>>>(bm, e, eh, sc);
    rank_select_kernel<<<(N0 + 255) / 256, 256>>>(sc, N0, KK0, idx0, vals0);
    gather_scale_split_kernel<<<(KK0 * DD + 255) / 256, 256>>>(X1d, idx0, vals0, KK0, X1s);

    gemm(KK0, DD, DD, X1s, DD, Ws + OFF_DW1, DD, db + DD, X2d, DD, nullptr, 0, nullptr, 0, 1);

    gemv_e_kernel<<<(KK0 + 7) / 8, 256>>>(KK0, X2d, pW + DD, pwb + 1, pb + 1, phi + 2, h1, e, eh);
    agg1_kernel<<<KK0, 256>>>(bm, idx0, KK0, e, eh, sc);
    rank_select_kernel<<<(KK0 + 255) / 256, 256>>>(sc, KK0, KK1, idx1, vals1);
    gather_scale_split_kernel<<<(KK1 * DD + 255) / 256, 256>>>(X2d, idx1, vals1, KK1, X2s);

    gemm(KK1, DD, DD, X2s, DD, Ws + OFF_WB, DD, bb, Xb, DD, nullptr, 0, nullptr, 0, 1);

    // ---- up level i=0 (u=1, n=KK0) ----
    zero_cols_split_kernel<<<(KK0 * DD + 255) / 256, 256>>>(catS, KK0);
    scatter_split_kernel<<<(KK1 * DD + 255) / 256, 256>>>(catS, idx1, Xb, KK1);
    copy_split_kernel<<<(KK0 * DD + 255) / 256, 256>>>(catS + DD, X2d, KK0);
    gemm(KK0, DD, DD2, catS, DD2, Ws + OFF_CATW0, DD, biasGS, nullptr, 0, Gs, DD, nullptr, 0, 1);
    gemm(KK0, DD, DD,  Gs,   DD,  Ws + OFF_AGP0,  DD, agbp, nullptr, 0, catS + DD, DD2, nullptr, 0, 2);
    gemm(KK0, DD, DD2, catS, DD2, Ws + OFF_UW0,   DD, ub,   Xu1, DD, nullptr, 0, X2d, DD, 1);

    // ---- up level i=1 (u=0, n=N0) ----
    zero_cols_split_kernel<<<(N0 * DD + 255) / 256, 256>>>(catS, N0);
    scatter_split_kernel<<<(KK0 * DD + 255) / 256, 256>>>(catS, idx0, Xu1, KK0);
    copy_split_kernel<<<(N0 * DD + 255) / 256, 256>>>(catS + DD, X1d, N0);
    gemm(N0, DD, DD2, catS, DD2, Ws + OFF_CATW1, DD, biasGS + DD, nullptr, 0, Gs, DD, nullptr, 0, 1);
    gemm(N0, DD, DD,  Gs,   DD,  Ws + OFF_AGP1,  DD, agbp + DD, nullptr, 0, catS + DD, DD2, nullptr, 0, 2);
    gemm(N0, DD, DD2, catS, DD2, Ws + OFF_UW1,   DD, ub + DD, Xu0, DD, nullptr, 0, X1d, DD, 1);

    // ---- head ----
    copy_split_kernel<<<(N0 * DD + 255) / 256, 256>>>(catS,      Xu0, N0);
    copy_split_kernel<<<(N0 * DD + 255) / 256, 256>>>(catS + DD, X0,  N0);
    gemm(N0, DD, DD2, catS, DD2, Ws + OFF_WE, DD, be, (float*)d_out, DD, nullptr, 0, nullptr, 0, 1);

    if (out_size >= 2 * N0 * DD) {
        cudaMemcpyAsync((float*)d_out + (size_t)N0 * DD, X0,
                        (size_t)N0 * DD * sizeof(float), cudaMemcpyDeviceToDevice, 0);
    }
}

// round 5
// speedup vs baseline: 1.1410x; 1.1410x over previous
#include <cuda_runtime.h>
#include <math.h>

#define N0   4096
#define DD   320
#define DD2  640
#define KK0  3276
#define KK1  1965
#define NW   128

__device__ float    g_part[2*N0*DD];
__device__ float    g_X0 [N0*DD];
__device__ float    g_X1d[N0*DD];
__device__ float    g_X2d[N0*DD];
__device__ float    g_Xb [N0*DD];
__device__ float    g_X1 [N0*DD];
__device__ float    g_X2 [N0*DD];
__device__ float    g_G  [N0*DD];
__device__ float    g_Xu1[N0*DD];
__device__ float    g_Xu0[N0*DD];
__device__ float    g_cat[N0*DD2];
__device__ unsigned g_bm [N0*NW];
__device__ float    g_h1 [N0];
__device__ float    g_e  [N0];
__device__ float    g_eh [N0];
__device__ float    g_sc [N0];
__device__ float    g_vals0[N0];
__device__ float    g_vals1[N0];
__device__ int      g_idx0[N0];
__device__ int      g_idx1[N0];
__device__ float    g_catW[2*DD2*DD];
__device__ float    g_biasGS[2*DD];

__device__ __forceinline__ unsigned tf32_rna(float x) {
    unsigned r;
    asm("cvt.rna.tf32.f32 %0, %1;" : "=r"(r) : "f"(x));
    return r;
}

__device__ __forceinline__ void mma_tf32(float* d, const unsigned* a, const unsigned* b) {
    asm volatile(
        "mma.sync.aligned.m16n8k8.row.col.f32.tf32.tf32.f32 "
        "{%0,%1,%2,%3}, {%4,%5,%6,%7}, {%8,%9}, {%0,%1,%2,%3};"
        : "+f"(d[0]), "+f"(d[1]), "+f"(d[2]), "+f"(d[3])
        : "r"(a[0]), "r"(a[1]), "r"(a[2]), "r"(a[3]), "r"(b[0]), "r"(b[1]));
}

__device__ __forceinline__ void cp_async16(unsigned daddr, const void* gptr, int src_bytes) {
    asm volatile("cp.async.cg.shared.global [%0], [%1], 16, %2;"
                 :: "r"(daddr), "l"(gptr), "r"(src_bytes));
}

__global__ void build_mask_kernel(const float* __restrict__ A, unsigned* __restrict__ bm) {
    int gid = blockIdx.x * blockDim.x + threadIdx.x;
    float v = A[gid];
    unsigned b = __ballot_sync(0xffffffffu, v != 0.0f);
    if ((threadIdx.x & 31) == 0) bm[gid >> 5] = b;
}

// ---------------------------------------------------------------------------
// 3xTF32 tensor-core GEMM, split-K over blockIdx.z (2 slices), raw partials.
// ---------------------------------------------------------------------------
#define APITCH 36
#define BPITCH 72

__global__ __launch_bounds__(128) void gemm_tc_kernel(
    int M, int N, int khalf,
    const float* __restrict__ A, int lda,
    const float* __restrict__ B, int ldb,
    float* __restrict__ P)
{
    __shared__ float As[2][64][APITCH];
    __shared__ float Bs[2][32][BPITCH];

    const int tid  = threadIdx.x;
    const int wid  = tid >> 5;
    const int lane = tid & 31;
    const int wm   = wid & 1;
    const int wn   = wid >> 1;
    const int g    = lane >> 2;
    const int tg   = lane & 3;

    const int row0  = blockIdx.y * 64;
    const int col0  = blockIdx.x * 64;
    const int kbase = blockIdx.z * khalf;

    unsigned asBase = (unsigned)__cvta_generic_to_shared(&As[0][0][0]);
    unsigned bsBase = (unsigned)__cvta_generic_to_shared(&Bs[0][0][0]);

    float acc[2][4][4];
#pragma unroll
    for (int mt = 0; mt < 2; mt++)
#pragma unroll
        for (int nt = 0; nt < 4; nt++)
#pragma unroll
            for (int j = 0; j < 4; j++) acc[mt][nt][j] = 0.f;

    const int nt_k = khalf / 32;

    auto issue_stage = [&](int kt, int s) {
        const int k0 = kbase + kt * 32;
#pragma unroll
        for (int i = 0; i < 4; i++) {
            int idx = i * 128 + tid;
            int r = idx >> 3, c4 = idx & 7;
            int gr = row0 + r;
            int pr = (gr < M) ? 16 : 0;
            int grc = gr < M ? gr : (M - 1);
            const float* gp = A + (size_t)grc * lda + k0 + c4 * 4;
            unsigned daddr = asBase + (unsigned)(((s * 64 + r) * APITCH + c4 * 4) * 4);
            cp_async16(daddr, gp, pr);
        }
#pragma unroll
        for (int i = 0; i < 4; i++) {
            int idx = i * 128 + tid;
            int kr = idx >> 4, c4 = idx & 15;
            const float* gp = B + (size_t)(k0 + kr) * ldb + col0 + c4 * 4;
            unsigned daddr = bsBase + (unsigned)(((s * 32 + kr) * BPITCH + c4 * 4) * 4);
            cp_async16(daddr, gp, 16);
        }
        asm volatile("cp.async.commit_group;");
    };

    issue_stage(0, 0);

    for (int kt = 0; kt < nt_k; kt++) {
        asm volatile("cp.async.wait_group 0;");
        __syncthreads();
        if (kt + 1 < nt_k) issue_stage(kt + 1, (kt + 1) & 1);

        const int buf = kt & 1;
        const float(*Asb)[APITCH] = As[buf];
        const float(*Bsb)[BPITCH] = Bs[buf];

#pragma unroll
        for (int kk = 0; kk < 4; kk++) {
            const int kc = kk * 8;
            unsigned abg[2][4], asm2[2][4];
#pragma unroll
            for (int mt = 0; mt < 2; mt++) {
                const int rb = wm * 32 + mt * 16;
                float x0 = Asb[rb + g][kc + tg];
                float x1 = Asb[rb + g + 8][kc + tg];
                float x2 = Asb[rb + g][kc + tg + 4];
                float x3 = Asb[rb + g + 8][kc + tg + 4];
                abg[mt][0] = tf32_rna(x0);
                abg[mt][1] = tf32_rna(x1);
                abg[mt][2] = tf32_rna(x2);
                abg[mt][3] = tf32_rna(x3);
                asm2[mt][0] = tf32_rna(x0 - __uint_as_float(abg[mt][0]));
                asm2[mt][1] = tf32_rna(x1 - __uint_as_float(abg[mt][1]));
                asm2[mt][2] = tf32_rna(x2 - __uint_as_float(abg[mt][2]));
                asm2[mt][3] = tf32_rna(x3 - __uint_as_float(abg[mt][3]));
            }
            unsigned bbg[4][2], bsm[4][2];
#pragma unroll
            for (int nt = 0; nt < 4; nt++) {
                const int cb = wn * 32 + nt * 8;
                float y0 = Bsb[kc + tg][cb + g];
                float y1 = Bsb[kc + tg + 4][cb + g];
                bbg[nt][0] = tf32_rna(y0);
                bbg[nt][1] = tf32_rna(y1);
                bsm[nt][0] = tf32_rna(y0 - __uint_as_float(bbg[nt][0]));
                bsm[nt][1] = tf32_rna(y1 - __uint_as_float(bbg[nt][1]));
            }
#pragma unroll
            for (int mt = 0; mt < 2; mt++)
#pragma unroll
                for (int nt = 0; nt < 4; nt++) {
                    mma_tf32(acc[mt][nt], abg[mt], bbg[nt]);
                    mma_tf32(acc[mt][nt], abg[mt], bsm[nt]);
                    mma_tf32(acc[mt][nt], asm2[mt], bbg[nt]);
                }
        }
        __syncthreads();
    }

    float* Pp = P + (size_t)blockIdx.z * M * N;
#pragma unroll
    for (int mt = 0; mt < 2; mt++) {
#pragma unroll
        for (int nt = 0; nt < 4; nt++) {
            const int col = col0 + wn * 32 + nt * 8 + tg * 2;
#pragma unroll
            for (int h = 0; h < 2; h++) {
                const int r = row0 + wm * 32 + mt * 16 + g + h * 8;
                if (r >= M) continue;
                float2* pp = reinterpret_cast<float2*>(Pp + (size_t)r * N + col);
                *pp = make_float2(acc[mt][nt][h * 2 + 0], acc[mt][nt][h * 2 + 1]);
            }
        }
    }
}

// C = act(P0 + P1 + bias) (+res after act)
__global__ void combine_kernel(int M, int N,
                               const float* __restrict__ P,
                               const float* __restrict__ bias,
                               float* __restrict__ C, int ldc,
                               const float* __restrict__ res, int ldres,
                               int act)
{
    int gid = blockIdx.x * blockDim.x + threadIdx.x;
    int total = (M * N) >> 2;
    if (gid >= total) return;
    int nq = N >> 2;
    int r = gid / nq;
    int c = (gid - r * nq) << 2;

    float4 p0 = reinterpret_cast<const float4*>(P)[gid];
    float4 p1 = reinterpret_cast<const float4*>(P + (size_t)M * N)[gid];
    float4 bv = *reinterpret_cast<const float4*>(bias + c);
    float v0 = p0.x + p1.x + bv.x;
    float v1 = p0.y + p1.y + bv.y;
    float v2 = p0.z + p1.z + bv.z;
    float v3 = p0.w + p1.w + bv.w;
    if (act == 1) {
        v0 = fmaxf(v0, 0.f); v1 = fmaxf(v1, 0.f);
        v2 = fmaxf(v2, 0.f); v3 = fmaxf(v3, 0.f);
    } else if (act == 2) {
        v0 = 1.f / (1.f + expf(-v0)); v1 = 1.f / (1.f + expf(-v1));
        v2 = 1.f / (1.f + expf(-v2)); v3 = 1.f / (1.f + expf(-v3));
    }
    if (res) {
        const float4 rv = *reinterpret_cast<const float4*>(res + (size_t)r * ldres + c);
        v0 += rv.x; v1 += rv.y; v2 += rv.z; v3 += rv.w;
    }
    *reinterpret_cast<float4*>(C + (size_t)r * ldc + c) = make_float4(v0, v1, v2, v3);
}

__global__ void gemv_e_kernel(int M, const float* __restrict__ X,
                              const float* __restrict__ w,
                              const float* __restrict__ pwb,
                              const float* __restrict__ pb,
                              const float* __restrict__ phi0,
                              float* __restrict__ h1,
                              float* __restrict__ e, float* __restrict__ eh)
{
    int warp = (blockIdx.x * blockDim.x + threadIdx.x) >> 5;
    int lane = threadIdx.x & 31;
    if (warp >= M) return;
    const float* xr = X + (size_t)warp * DD;
    float s = 0.f;
    for (int k = lane; k < DD; k += 32) s += xr[k] * w[k];
#pragma unroll
    for (int o = 16; o > 0; o >>= 1) s += __shfl_down_sync(0xffffffffu, s, o);
    if (lane == 0) {
        float h = s + pwb[0] + pb[0];
        float ex = expf(phi0[0] * h);
        h1[warp] = h;
        e[warp] = ex;
        eh[warp] = ex * h;
    }
}

__global__ void agg0_kernel(const unsigned* __restrict__ bm,
                            const float* __restrict__ e,
                            const float* __restrict__ eh,
                            float* __restrict__ scores)
{
    int r = blockIdx.x;
    int t = threadIdx.x;
    unsigned w = bm[r * NW + t];
    if ((r >> 5) == t) w |= (1u << (r & 31));
    float se = 0.f, sh = 0.f;
    while (w) {
        int b = __ffs(w) - 1;
        w &= w - 1;
        int j = t * 32 + b;
        se += e[j];
        sh += eh[j];
    }
    __shared__ float s1[128], s2[128];
    s1[t] = se; s2[t] = sh;
    __syncthreads();
    for (int o = 64; o > 0; o >>= 1) {
        if (t < o) { s1[t] += s1[t + o]; s2[t] += s2[t + o]; }
        __syncthreads();
    }
    if (t == 0) {
        float agg = (s2[0] / s1[0]) * 0.01f;
        scores[r] = 1.f / (1.f + expf(-agg));
    }
}

__global__ void agg1_kernel(const unsigned* __restrict__ bm,
                            const int* __restrict__ idx0, int n1,
                            const float* __restrict__ e,
                            const float* __restrict__ eh,
                            float* __restrict__ scores)
{
    __shared__ unsigned row[NW];
    int r = blockIdx.x;
    int t = threadIdx.x;
    int orig = idx0[r];
    if (t < NW) row[t] = bm[orig * NW + t];
    __syncthreads();
    float se = 0.f, sh = 0.f;
    for (int j = t; j < n1; j += 256) {
        int c = idx0[j];
        bool in = (row[c >> 5] >> (c & 31)) & 1u;
        if (j == r) in = true;
        if (in) { se += e[j]; sh += eh[j]; }
    }
    __shared__ float s1[256], s2[256];
    s1[t] = se; s2[t] = sh;
    __syncthreads();
    for (int o = 128; o > 0; o >>= 1) {
        if (t < o) { s1[t] += s1[t + o]; s2[t] += s2[t + o]; }
        __syncthreads();
    }
    if (t == 0) {
        float agg = (s2[0] / s1[0]) * 0.01f;
        scores[r] = 1.f / (1.f + expf(-agg));
    }
}

__global__ void rank_select_kernel(const float* __restrict__ s, int n, int kk,
                                   int* __restrict__ idx, float* __restrict__ vals)
{
    __shared__ float sh[256];
    int i = blockIdx.x * blockDim.x + threadIdx.x;
    float si = (i < n) ? s[i] : 0.f;
    int rank = 0;
    for (int base = 0; base < n; base += 256) {
        int j = base + threadIdx.x;
        sh[threadIdx.x] = (j < n) ? s[j] : -3.0e38f;
        __syncthreads();
        int lim = min(256, n - base);
        for (int t = 0; t < lim; t++) {
            float sj = sh[t];
            int j2 = base + t;
            if (sj > si || (sj == si && j2 < i)) rank++;
        }
        __syncthreads();
    }
    if (i < n && rank < kk) { idx[rank] = i; vals[rank] = si; }
}

__global__ void gather_scale_kernel(const float* __restrict__ src,
                                    const int* __restrict__ idx,
                                    const float* __restrict__ vals,
                                    int rows, float* __restrict__ dst)
{
    int gid = blockIdx.x * blockDim.x + threadIdx.x;
    if (gid >= rows * DD) return;
    int r = gid / DD, c = gid % DD;
    dst[gid] = src[(size_t)idx[r] * DD + c] * vals[r];
}

__global__ void zero_kernel(float* __restrict__ p, int n) {
    int gid = blockIdx.x * blockDim.x + threadIdx.x;
    if (gid < n) p[gid] = 0.f;
}

__global__ void scatter_kernel(float* __restrict__ dst, int ldd,
                               const int* __restrict__ idx,
                               const float* __restrict__ src, int rows)
{
    int gid = blockIdx.x * blockDim.x + threadIdx.x;
    if (gid >= rows * DD) return;
    int r = gid / DD, c = gid % DD;
    dst[(size_t)idx[r] * ldd + c] = src[gid];
}

__global__ void copy_block_kernel(float* __restrict__ dst, int ldd,
                                  const float* __restrict__ src, int lds, int rows)
{
    int gid = blockIdx.x * blockDim.x + threadIdx.x;
    if (gid >= rows * DD) return;
    int r = gid / DD, c = gid % DD;
    dst[(size_t)r * ldd + c] = src[(size_t)r * lds + c];
}

__global__ void add_bias_kernel(const float* __restrict__ a,
                                const float* __restrict__ b,
                                float* __restrict__ o, int n)
{
    int gid = blockIdx.x * blockDim.x + threadIdx.x;
    if (gid < n) o[gid] = a[gid] + b[gid];
}

extern "C" void kernel_launch(void* const* d_in, const int* in_sizes, int n_in,
                              void* d_out, int out_size)
{
    const float* A     = (const float*)d_in[0];
    const float* Xin   = (const float*)d_in[1];
    const float* W0    = (const float*)d_in[2];
    const float* b0    = (const float*)d_in[3];
    const float* Wb    = (const float*)d_in[4];
    const float* bb    = (const float*)d_in[5];
    const float* We    = (const float*)d_in[6];
    const float* be    = (const float*)d_in[7];
    const float* dW    = (const float*)d_in[8];
    const float* db    = (const float*)d_in[9];
    const float* uW    = (const float*)d_in[10];
    const float* ub    = (const float*)d_in[11];
    const float* pW    = (const float*)d_in[12];
    const float* pwb   = (const float*)d_in[13];
    const float* pb    = (const float*)d_in[14];
    const float* phi   = (const float*)d_in[15];
    const float* agWg  = (const float*)d_in[16];
    const float* agbg  = (const float*)d_in[17];
    const float* agWs  = (const float*)d_in[18];
    const float* agbs  = (const float*)d_in[19];
    const float* agWp  = (const float*)d_in[20];
    const float* agbp  = (const float*)d_in[21];

    float *part, *X0, *X1d, *X2d, *Xb, *X1, *X2, *G, *Xu1, *Xu0, *cat;
    float *h1, *e, *eh, *sc, *vals0, *vals1, *catW, *biasGS;
    int *idx0, *idx1;
    unsigned* bm;
    cudaGetSymbolAddress((void**)&part, g_part);
    cudaGetSymbolAddress((void**)&X0,  g_X0);
    cudaGetSymbolAddress((void**)&X1d, g_X1d);
    cudaGetSymbolAddress((void**)&X2d, g_X2d);
    cudaGetSymbolAddress((void**)&Xb,  g_Xb);
    cudaGetSymbolAddress((void**)&X1,  g_X1);
    cudaGetSymbolAddress((void**)&X2,  g_X2);
    cudaGetSymbolAddress((void**)&G,   g_G);
    cudaGetSymbolAddress((void**)&Xu1, g_Xu1);
    cudaGetSymbolAddress((void**)&Xu0, g_Xu0);
    cudaGetSymbolAddress((void**)&cat, g_cat);
    cudaGetSymbolAddress((void**)&bm,  g_bm);
    cudaGetSymbolAddress((void**)&h1,  g_h1);
    cudaGetSymbolAddress((void**)&e,   g_e);
    cudaGetSymbolAddress((void**)&eh,  g_eh);
    cudaGetSymbolAddress((void**)&sc,  g_sc);
    cudaGetSymbolAddress((void**)&vals0, g_vals0);
    cudaGetSymbolAddress((void**)&vals1, g_vals1);
    cudaGetSymbolAddress((void**)&idx0, g_idx0);
    cudaGetSymbolAddress((void**)&idx1, g_idx1);
    cudaGetSymbolAddress((void**)&catW, g_catW);
    cudaGetSymbolAddress((void**)&biasGS, g_biasGS);

    const int WMAT = DD * DD;

    auto gemm = [&](int M, int N, int K,
                    const float* Ap, int lda, const float* Bp, int ldb,
                    const float* bias, float* Cp, int ldc,
                    const float* res, int ldres, int act) {
        dim3 grid(N / 64, (M + 63) / 64, 2);
        gemm_tc_kernel<<<grid, 128>>>(M, N, K / 2, Ap, lda, Bp, ldb, part);
        int total = (M * N) / 4;
        combine_kernel<<<(total + 255) / 256, 256>>>(M, N, part, bias, Cp, ldc,
                                                     res, ldres, act);
    };

    // ---- setup ----
    build_mask_kernel<<<(N0 * N0) / 256, 256>>>(A, bm);
    add_bias_kernel<<<3, 256>>>(agbg, agbs, biasGS, 2 * DD);
    cudaMemcpyAsync(catW,            agWg,        WMAT * 4, cudaMemcpyDeviceToDevice, 0);
    cudaMemcpyAsync(catW + WMAT,     agWs,        WMAT * 4, cudaMemcpyDeviceToDevice, 0);
    cudaMemcpyAsync(catW + 2 * WMAT, agWg + WMAT, WMAT * 4, cudaMemcpyDeviceToDevice, 0);
    cudaMemcpyAsync(catW + 3 * WMAT, agWs + WMAT, WMAT * 4, cudaMemcpyDeviceToDevice, 0);

    // ---- encoder / down path ----
    gemm(N0, DD, DD, Xin, DD, W0, DD, b0, X0, DD, nullptr, 0, 1);
    gemm(N0, DD, DD, X0, DD, dW, DD, db, X1d, DD, nullptr, 0, 1);

    gemv_e_kernel<<<(N0 + 7) / 8, 256>>>(N0, X1d, pW, pwb, pb, phi, h1, e, eh);
    agg0_kernel<<<N0, 128>>>(bm, e, eh, sc);
    rank_select_kernel<<<(N0 + 255) / 256, 256>>>(sc, N0, KK0, idx0, vals0);
    gather_scale_kernel<<<(KK0 * DD + 255) / 256, 256>>>(X1d, idx0, vals0, KK0, X1);

    gemm(KK0, DD, DD, X1, DD, dW + WMAT, DD, db + DD, X2d, DD, nullptr, 0, 1);

    gemv_e_kernel<<<(KK0 + 7) / 8, 256>>>(KK0, X2d, pW + DD, pwb + 1, pb + 1, phi + 2, h1, e, eh);
    agg1_kernel<<<KK0, 256>>>(bm, idx0, KK0, e, eh, sc);
    rank_select_kernel<<<(KK0 + 255) / 256, 256>>>(sc, KK0, KK1, idx1, vals1);
    gather_scale_kernel<<<(KK1 * DD + 255) / 256, 256>>>(X2d, idx1, vals1, KK1, X2);

    gemm(KK1, DD, DD, X2, DD, Wb, DD, bb, Xb, DD, nullptr, 0, 1);

    // ---- up level i=0 (u=1, n=KK0) ----
    zero_kernel<<<(KK0 * DD2 + 255) / 256, 256>>>(cat, KK0 * DD2);
    scatter_kernel<<<(KK1 * DD + 255) / 256, 256>>>(cat, DD2, idx1, Xb, KK1);
    copy_block_kernel<<<(KK0 * DD + 255) / 256, 256>>>(cat + DD, DD2, X2d, DD, KK0);
    gemm(KK0, DD, DD2, cat, DD2, catW, DD, biasGS, G, DD, nullptr, 0, 1);
    gemm(KK0, DD, DD,  G,   DD,  agWp, DD, agbp, cat + DD, DD2, nullptr, 0, 2);
    gemm(KK0, DD, DD2, cat, DD2, uW,   DD, ub,   Xu1, DD, X2d, DD, 1);

    // ---- up level i=1 (u=0, n=N0) ----
    zero_kernel<<<(N0 * DD2 + 255) / 256, 256>>>(cat, N0 * DD2);
    scatter_kernel<<<(KK0 * DD + 255) / 256, 256>>>(cat, DD2, idx0, Xu1, KK0);
    copy_block_kernel<<<(N0 * DD + 255) / 256, 256>>>(cat + DD, DD2, X1d, DD, N0);
    gemm(N0, DD, DD2, cat, DD2, catW + 2 * WMAT, DD, biasGS + DD, G, DD, nullptr, 0, 1);
    gemm(N0, DD, DD,  G,   DD,  agWp + WMAT, DD, agbp + DD, cat + DD, DD2, nullptr, 0, 2);
    gemm(N0, DD, DD2, cat, DD2, uW + 2 * WMAT, DD, ub + DD, Xu0, DD, X1d, DD, 1);

    // ---- head ----
    copy_block_kernel<<<(N0 * DD + 255) / 256, 256>>>(cat,      DD2, Xu0, DD, N0);
    copy_block_kernel<<<(N0 * DD + 255) / 256, 256>>>(cat + DD, DD2, X0,  DD, N0);
    gemm(N0, DD, DD2, cat, DD2, We, DD, be, (float*)d_out, DD, nullptr, 0, 1);

    if (out_size >= 2 * N0 * DD) {
        cudaMemcpyAsync((float*)d_out + (size_t)N0 * DD, X0,
                        (size_t)N0 * DD * sizeof(float), cudaMemcpyDeviceToDevice, 0);
    }
}